// round 1
// baseline (speedup 1.0000x reference)
#include <cuda_runtime.h>

#define N_ 4
#define C_ 256
#define H_ 200
#define W_ 272
#define O_ 7

// Integral image in TRANSPOSED layout [n][h][w][c] so the per-ROI gather of
// 256-channel corner vectors is a contiguous, coalesced 1KB load.
__device__ float g_integ[(size_t)N_ * H_ * W_ * C_];

// --------------------------------------------------------------------------
// Kernel A: H-direction prefix sum + transpose.
//   in : fm[n][c][h][w]           (coalesced reads along w)
//   out: g_integ[n][h][w][c] = sum_{h'<=h} fm[n][c][h'][w]   (coalesced writes along c)
// Grid: (ceil(W/32), C/32, N). Block: 256 threads. Smem-staged transpose.
// --------------------------------------------------------------------------
__global__ void hscan_transpose(const float* __restrict__ fm) {
    __shared__ float tile[32 * 33];   // padded to kill bank conflicts

    const int w0 = blockIdx.x * 32;
    const int c0 = blockIdx.y * 32;
    const int n  = blockIdx.z;

    const int tx  = threadIdx.x & 31;   // w within tile (load phase)
    const int ty  = threadIdx.x >> 5;   // 0..7
    const int wl  = w0 + tx;
    const bool wok = (wl < W_);

    const int c2  = threadIdx.x & 31;   // c within tile (store phase)
    const int w2b = threadIdx.x >> 5;   // 0..7

    float acc[4] = {0.f, 0.f, 0.f, 0.f};

    const size_t in_base  = ((size_t)n * C_ + c0) * H_ * W_;   // + (c_l*H + h)*W + wl
    const size_t out_base = (size_t)n * H_ * W_ * C_;          // + (h*W + w)*C + c

    for (int h = 0; h < H_; ++h) {
        #pragma unroll
        for (int k = 0; k < 4; ++k) {
            const int cl = ty + 8 * k;
            float v = 0.f;
            if (wok) v = fm[in_base + ((size_t)cl * H_ + h) * W_ + wl];
            acc[k] += v;
            tile[cl * 33 + tx] = acc[k];
        }
        __syncthreads();
        #pragma unroll
        for (int k = 0; k < 4; ++k) {
            const int w2 = w2b + 8 * k;
            if (w0 + w2 < W_) {
                g_integ[out_base + ((size_t)h * W_ + (w0 + w2)) * C_ + c0 + c2] =
                    tile[c2 * 33 + w2];
            }
        }
        __syncthreads();
    }
}

// --------------------------------------------------------------------------
// Kernel B: W-direction prefix sum, in place, on g_integ[n][h][w][c].
// Block per (n,h); thread = channel. Chunked 8-wide so the 8 loads of each
// chunk are independent (MLP=8) and overlap the previous chunk's stores.
// --------------------------------------------------------------------------
__global__ void wscan() {
    const size_t base = (size_t)blockIdx.x * W_ * C_ + threadIdx.x;
    float acc = 0.f;
    for (int w0 = 0; w0 < W_; w0 += 8) {
        float v[8];
        #pragma unroll
        for (int k = 0; k < 8; ++k)
            v[k] = g_integ[base + (size_t)(w0 + k) * C_];
        #pragma unroll
        for (int k = 0; k < 8; ++k) { acc += v[k]; v[k] = acc; }
        #pragma unroll
        for (int k = 0; k < 8; ++k)
            g_integ[base + (size_t)(w0 + k) * C_] = v[k];
    }
}

// --------------------------------------------------------------------------
// Kernel C: per-ROI gather. Block per ROI, thread per channel.
// corner(hi,wi) = (hi>0 && wi>0) ? integ[hi-1][wi-1] : 0  (zero-pad semantics)
// --------------------------------------------------------------------------
__global__ void roipool(const int* __restrict__ rois, float* __restrict__ out,
                        int img_off, int R) {
    const int r = blockIdx.x;
    if (r >= R) return;
    const int c = threadIdx.x;

    const int n  = rois[r * 5 + 0];
    const int x1 = rois[r * 5 + 1];
    const int y1 = rois[r * 5 + 2];
    const int x2 = rois[r * 5 + 3];
    const int y2 = rois[r * 5 + 4];

    const int hin = y2 - y1 + 1;
    const int win = x2 - x1 + 1;

    int hs[O_], he[O_], ws[O_], we[O_];
    #pragma unroll
    for (int i = 0; i < O_; ++i) {
        hs[i] = y1 + (i * hin) / O_;
        he[i] = y1 + ((i + 1) * hin + O_ - 1) / O_;
        ws[i] = x1 + (i * win) / O_;
        we[i] = x1 + ((i + 1) * win + O_ - 1) / O_;
    }

    const float* base = g_integ + (size_t)n * H_ * W_ * C_ + c;
    float* o = out + img_off + ((size_t)r * C_ + c) * (O_ * O_);

    if (img_off > 0 && c == 0) out[r] = (float)n;   // img_idx output (cast)

    #pragma unroll
    for (int i = 0; i < O_; ++i) {
        const int hiT = hs[i];   // top (exclusive-prefix index)
        const int hiB = he[i];   // bottom
        const float hd = (float)(hiB - hiT);
        #pragma unroll
        for (int j = 0; j < O_; ++j) {
            const int wiL = ws[j];
            const int wiR = we[j];

            float cBR = base[((size_t)(hiB - 1) * W_ + (wiR - 1)) * C_];
            float cTR = (hiT > 0) ? base[((size_t)(hiT - 1) * W_ + (wiR - 1)) * C_] : 0.f;
            float cBL = (wiL > 0) ? base[((size_t)(hiB - 1) * W_ + (wiL - 1)) * C_] : 0.f;
            float cTL = (hiT > 0 && wiL > 0)
                            ? base[((size_t)(hiT - 1) * W_ + (wiL - 1)) * C_] : 0.f;

            const float s    = (cBR - cTR) - (cBL - cTL);
            const float area = hd * (float)(wiR - wiL);
            o[i * O_ + j] = s / area;
        }
    }
}

// --------------------------------------------------------------------------
extern "C" void kernel_launch(void* const* d_in, const int* in_sizes, int n_in,
                              void* d_out, int out_size) {
    const float* fm   = (const float*)d_in[0];
    const int*   rois = (const int*)d_in[1];
    const int R = in_sizes[1] / 5;

    // Tuple output (img_idx, out): detect whether img_idx occupies a prefix.
    int img_off = out_size - R * C_ * O_ * O_;
    if (img_off < 0) img_off = 0;

    dim3 gA((W_ + 31) / 32, C_ / 32, N_);
    hscan_transpose<<<gA, 256>>>(fm);
    wscan<<<N_ * H_, 256>>>();
    roipool<<<R, 256>>>(rois, (float*)d_out, img_off, R);
}

// round 2
// speedup vs baseline: 1.0119x; 1.0119x over previous
#include <cuda_runtime.h>

#define N_ 4
#define C_ 256
#define H_ 200
#define W_ 272
#define O_ 7
#define K_CH 8          // h-chunks
#define HCH 25          // H_ / K_CH

// Chunk-local 2D integral image, TRANSPOSED layout [n][h][w][c]
// (h = k*HCH + lh; integral restarted at each chunk boundary in h).
__device__ float g_integ[(size_t)N_ * H_ * W_ * C_];
// carry[n][k][w][c] = full column prefix (w-scanned) of all chunks above k.
__device__ float g_carry[(size_t)N_ * K_CH * W_ * C_];

// --------------------------------------------------------------------------
// Fused H-scan + W-scan + transpose, one pass over the data.
// Block: 288 threads, thread = w (272 active). Block owns (n, h-chunk k, 8 c).
// Per h row: 8 coalesced row loads, acc[j] += v (H-scan), block shuffle scan
// across w (W-scan), 2x float4 contiguous store per thread (full 32B sectors).
// Grid: (C_/8, K_CH, N_) = (32, 8, 4) = 1024 blocks.
// --------------------------------------------------------------------------
__global__ __launch_bounds__(288) void fused_scan(const float* __restrict__ fm) {
    __shared__ float wsum[2][8][9];   // double-buffered warp sums

    const int c0 = blockIdx.x * 8;
    const int k  = blockIdx.y;
    const int n  = blockIdx.z;
    const int w    = threadIdx.x;
    const int lane = w & 31;
    const int wid  = w >> 5;          // 0..8
    const bool active = (w < W_);

    float acc[8] = {0.f,0.f,0.f,0.f,0.f,0.f,0.f,0.f};

    const size_t in_base  = (((size_t)n * C_ + c0) * H_ + (size_t)k * HCH) * W_ + w;
    const size_t out_base = (((size_t)n * H_ + (size_t)k * HCH) * W_) * C_ + c0;

    for (int lh = 0; lh < HCH; ++lh) {
        const int buf = lh & 1;
        float s[8];
        // 8 independent coalesced loads (MLP=8 per thread)
        #pragma unroll
        for (int j = 0; j < 8; ++j)
            s[j] = active ? fm[in_base + ((size_t)j * H_ + lh) * W_] : 0.f;

        // H-scan in registers + per-warp inclusive W-scan
        #pragma unroll
        for (int j = 0; j < 8; ++j) {
            acc[j] += s[j];
            float x = acc[j];
            #pragma unroll
            for (int d = 1; d < 32; d <<= 1) {
                float y = __shfl_up_sync(0xffffffff, x, d);
                if (lane >= d) x += y;
            }
            s[j] = x;
            if (lane == 31) wsum[buf][j][wid] = x;
        }
        __syncthreads();

        // add exclusive prefix of warp sums (broadcast smem reads)
        #pragma unroll
        for (int j = 0; j < 8; ++j) {
            float p = 0.f;
            #pragma unroll
            for (int t = 0; t < 8; ++t)
                if (t < wid) p += wsum[buf][j][t];
            s[j] += p;
        }

        if (active) {
            float* dst = &g_integ[out_base + ((size_t)lh * W_ + w) * C_];
            float4 lo = make_float4(s[0], s[1], s[2], s[3]);
            float4 hi = make_float4(s[4], s[5], s[6], s[7]);
            ((float4*)dst)[0] = lo;
            ((float4*)dst)[1] = hi;
        }
        // next iteration uses the other wsum buffer; the barrier above
        // already ordered this iteration's reads before iter+2's writes.
    }
}

// --------------------------------------------------------------------------
// carry[n][k][w][c] = exclusive prefix over chunks of the last row of each
// chunk-local integral (i.e. full column sums above chunk k, w-scanned).
// Thread per (n,w,c), coalesced in c. ~11 MB traffic -> microseconds.
// --------------------------------------------------------------------------
__global__ void chunk_carry() {
    const int total = N_ * W_ * C_;
    int idx = blockIdx.x * 256 + threadIdx.x;
    if (idx >= total) return;
    const int c = idx % C_;
    const int w = (idx / C_) % W_;
    const int n = idx / (C_ * W_);

    float p = 0.f;
    #pragma unroll
    for (int k = 0; k < K_CH; ++k) {
        g_carry[(((size_t)n * K_CH + k) * W_ + w) * C_ + c] = p;
        p += g_integ[(((size_t)n * H_ + (size_t)k * HCH + (HCH - 1)) * W_ + w) * C_ + c];
    }
}

// --------------------------------------------------------------------------
// Per-ROI gather. Block per ROI, thread per channel.
// corner(hi,wi) for hi,wi in prefix space (0 row/col = zero pad):
//   k = (hi-1)/HCH; value = chunk_integ[hi-1][wi-1][c] + carry[k][wi-1][c]
// --------------------------------------------------------------------------
__global__ void roipool(const int* __restrict__ rois, float* __restrict__ out,
                        int img_off, int R) {
    const int r = blockIdx.x;
    if (r >= R) return;
    const int c = threadIdx.x;

    const int n  = rois[r * 5 + 0];
    const int x1 = rois[r * 5 + 1];
    const int y1 = rois[r * 5 + 2];
    const int x2 = rois[r * 5 + 3];
    const int y2 = rois[r * 5 + 4];

    const int hin = y2 - y1 + 1;
    const int win = x2 - x1 + 1;

    int hs[O_], he[O_], ws[O_], we[O_];
    #pragma unroll
    for (int i = 0; i < O_; ++i) {
        hs[i] = y1 + (i * hin) / O_;
        he[i] = y1 + ((i + 1) * hin + O_ - 1) / O_;
        ws[i] = x1 + (i * win) / O_;
        we[i] = x1 + ((i + 1) * win + O_ - 1) / O_;
    }

    const float* ibase = g_integ + (size_t)n * H_ * W_ * C_ + c;
    const float* cbase = g_carry + (size_t)n * K_CH * W_ * C_ + c;
    float* o = out + img_off + ((size_t)r * C_ + c) * (O_ * O_);

    if (img_off > 0 && c == 0) out[r] = (float)n;   // img_idx output

    #pragma unroll
    for (int i = 0; i < O_; ++i) {
        const int hiT = hs[i];
        const int hiB = he[i];
        const int kB  = (hiB - 1) / HCH;
        const int kT  = (hiT > 0) ? (hiT - 1) / HCH : 0;
        const float hd = (float)(hiB - hiT);
        #pragma unroll
        for (int j = 0; j < O_; ++j) {
            const int wL = ws[j] - 1;   // may be -1 (pad)
            const int wR = we[j] - 1;   // >= 0 always

            float cBR = ibase[((size_t)(hiB - 1) * W_ + wR) * C_]
                      + cbase[((size_t)kB * W_ + wR) * C_];
            float cTR = (hiT > 0)
                      ? ibase[((size_t)(hiT - 1) * W_ + wR) * C_]
                      + cbase[((size_t)kT * W_ + wR) * C_] : 0.f;
            float cBL = (wL >= 0)
                      ? ibase[((size_t)(hiB - 1) * W_ + wL) * C_]
                      + cbase[((size_t)kB * W_ + wL) * C_] : 0.f;
            float cTL = (hiT > 0 && wL >= 0)
                      ? ibase[((size_t)(hiT - 1) * W_ + wL) * C_]
                      + cbase[((size_t)kT * W_ + wL) * C_] : 0.f;

            const float s    = (cBR - cTR) - (cBL - cTL);
            const float area = hd * (float)(we[j] - ws[j]);
            o[i * O_ + j] = s / area;
        }
    }
}

// --------------------------------------------------------------------------
extern "C" void kernel_launch(void* const* d_in, const int* in_sizes, int n_in,
                              void* d_out, int out_size) {
    const float* fm   = (const float*)d_in[0];
    const int*   rois = (const int*)d_in[1];
    const int R = in_sizes[1] / 5;

    int img_off = out_size - R * C_ * O_ * O_;
    if (img_off < 0) img_off = 0;

    dim3 gF(C_ / 8, K_CH, N_);
    fused_scan<<<gF, 288>>>(fm);

    const int tot = N_ * W_ * C_;
    chunk_carry<<<(tot + 255) / 256, 256>>>();

    roipool<<<R, 256>>>(rois, (float*)d_out, img_off, R);
}

// round 3
// speedup vs baseline: 1.1935x; 1.1794x over previous
#include <cuda_runtime.h>

#define N_ 4
#define C_ 256
#define H_ 200
#define W_ 272
#define O_ 7
#define K_CH 8          // h-chunks
#define HCH 25          // H_ / K_CH

// Chunk-local 2D integral image, TRANSPOSED layout [n][h][w][c].
__device__ float g_integ[(size_t)N_ * H_ * W_ * C_];
// carry[n][k][w][c] = w-scanned column prefix of all chunks above k.
__device__ float g_carry[(size_t)N_ * K_CH * W_ * C_];

// --------------------------------------------------------------------------
// Fused H-scan + W-scan + transpose, one pass.
// Block: 160 threads (5 warps), thread = pair of w (136 active). Block owns
// (n, h-chunk k, 8 channels). Per row: 8 float2 loads, H-scan in registers,
// in-thread pair scan + warp shuffle scan of pair totals + smem block
// combine, 4x STG.128 c-major stores.
// --------------------------------------------------------------------------
__global__ __launch_bounds__(160) void fused_scan(const float* __restrict__ fm) {
    __shared__ float wsum[2][8][8];   // [buf][channel][warp], 5 warps used

    const int c0 = blockIdx.x * 8;
    const int k  = blockIdx.y;
    const int n  = blockIdx.z;
    const int slot = threadIdx.x;     // 0..159, active < 136
    const int lane = slot & 31;
    const int wid  = slot >> 5;       // 0..4
    const bool active = (slot < 136);
    const int w0 = slot * 2;

    float2 acc[8];
    #pragma unroll
    for (int j = 0; j < 8; ++j) acc[j] = make_float2(0.f, 0.f);

    const float* in0 = fm + ((size_t)(n * C_ + c0) * H_ + (size_t)k * HCH) * W_
                          + (active ? w0 : 0);
    const size_t out_base = (((size_t)n * H_ + (size_t)k * HCH) * W_) * C_ + c0;

    for (int lh = 0; lh < HCH; ++lh) {
        const int buf = lh & 1;
        float2 v[8];
        #pragma unroll
        for (int j = 0; j < 8; ++j)
            v[j] = *(const float2*)(in0 + (size_t)j * (H_ * W_) + (size_t)lh * W_);

        float slo[8], shi[8];
        #pragma unroll
        for (int j = 0; j < 8; ++j) {
            if (!active) { v[j].x = 0.f; v[j].y = 0.f; }
            acc[j].x += v[j].x;
            acc[j].y += v[j].y;
            const float lo  = acc[j].x;
            const float tot = acc[j].x + acc[j].y;
            float x = tot;                       // inclusive warp scan
            #pragma unroll
            for (int d = 1; d < 32; d <<= 1) {
                float y = __shfl_up_sync(0xffffffff, x, d);
                if (lane >= d) x += y;
            }
            const float excl = x - tot;
            slo[j] = lo + excl;
            shi[j] = tot + excl;
            if (lane == 31) wsum[buf][j][wid] = x;   // warp total
        }
        __syncthreads();

        #pragma unroll
        for (int j = 0; j < 8; ++j) {
            float p = 0.f;
            #pragma unroll
            for (int t = 0; t < 4; ++t)
                if (t < wid) p += wsum[buf][j][t];
            slo[j] += p;
            shi[j] += p;
        }

        if (active) {
            float* dst = &g_integ[out_base + ((size_t)lh * W_ + w0) * C_];
            ((float4*)dst)[0] = make_float4(slo[0], slo[1], slo[2], slo[3]);
            ((float4*)dst)[1] = make_float4(slo[4], slo[5], slo[6], slo[7]);
            float* dst2 = dst + C_;
            ((float4*)dst2)[0] = make_float4(shi[0], shi[1], shi[2], shi[3]);
            ((float4*)dst2)[1] = make_float4(shi[4], shi[5], shi[6], shi[7]);
        }
        // double-buffered wsum: one barrier per row is sufficient
    }
}

// --------------------------------------------------------------------------
// carry[n][k][w][c]: exclusive prefix over chunks of each chunk's last row.
// --------------------------------------------------------------------------
__global__ void chunk_carry() {
    const int total = N_ * W_ * C_;
    int idx = blockIdx.x * 256 + threadIdx.x;
    if (idx >= total) return;
    const int c = idx % C_;
    const int w = (idx / C_) % W_;
    const int n = idx / (C_ * W_);

    float p = 0.f;
    #pragma unroll
    for (int k = 0; k < K_CH; ++k) {
        g_carry[(((size_t)n * K_CH + k) * W_ + w) * C_ + c] = p;
        p += g_integ[(((size_t)n * H_ + (size_t)k * HCH + (HCH - 1)) * W_ + w) * C_ + c];
    }
}

// --------------------------------------------------------------------------
// Per-ROI gather. Block per ROI, thread per channel.
// Results staged in dynamic smem, then written out coalesced (float4).
// --------------------------------------------------------------------------
__global__ void roipool(const int* __restrict__ rois, float* __restrict__ out,
                        int img_off, int R) {
    extern __shared__ float stage[];   // 256 * 49 floats = 50176 B
    const int r = blockIdx.x;
    if (r >= R) return;
    const int c = threadIdx.x;

    const int n  = rois[r * 5 + 0];
    const int x1 = rois[r * 5 + 1];
    const int y1 = rois[r * 5 + 2];
    const int x2 = rois[r * 5 + 3];
    const int y2 = rois[r * 5 + 4];

    const int hin = y2 - y1 + 1;
    const int win = x2 - x1 + 1;

    int hs[O_], he[O_], ws[O_], we[O_];
    #pragma unroll
    for (int i = 0; i < O_; ++i) {
        hs[i] = y1 + (i * hin) / O_;
        he[i] = y1 + ((i + 1) * hin + O_ - 1) / O_;
        ws[i] = x1 + (i * win) / O_;
        we[i] = x1 + ((i + 1) * win + O_ - 1) / O_;
    }

    const float* ibase = g_integ + (size_t)n * H_ * W_ * C_ + c;
    const float* cbase = g_carry + (size_t)n * K_CH * W_ * C_ + c;

    if (img_off > 0 && c == 0) out[r] = (float)n;   // img_idx output

    #pragma unroll
    for (int i = 0; i < O_; ++i) {
        const int hiT = hs[i];
        const int hiB = he[i];
        const int kB  = (hiB - 1) / HCH;
        const int kT  = (hiT > 0) ? (hiT - 1) / HCH : 0;
        const float hd = (float)(hiB - hiT);
        #pragma unroll
        for (int j = 0; j < O_; ++j) {
            const int wL = ws[j] - 1;   // may be -1 (pad)
            const int wR = we[j] - 1;

            float cBR = ibase[((size_t)(hiB - 1) * W_ + wR) * C_]
                      + cbase[((size_t)kB * W_ + wR) * C_];
            float cTR = (hiT > 0)
                      ? ibase[((size_t)(hiT - 1) * W_ + wR) * C_]
                      + cbase[((size_t)kT * W_ + wR) * C_] : 0.f;
            float cBL = (wL >= 0)
                      ? ibase[((size_t)(hiB - 1) * W_ + wL) * C_]
                      + cbase[((size_t)kB * W_ + wL) * C_] : 0.f;
            float cTL = (hiT > 0 && wL >= 0)
                      ? ibase[((size_t)(hiT - 1) * W_ + wL) * C_]
                      + cbase[((size_t)kT * W_ + wL) * C_] : 0.f;

            const float s    = (cBR - cTR) - (cBL - cTL);
            const float area = hd * (float)(we[j] - ws[j]);
            stage[c * (O_ * O_) + i * O_ + j] = s / area;   // stride 49: conflict-free
        }
    }
    __syncthreads();

    // coalesced float4 writeout of the whole 49KB tile
    float4* o4 = (float4*)(out + img_off + (size_t)r * (C_ * O_ * O_));
    const float4* s4 = (const float4*)stage;
    const int n4 = C_ * O_ * O_ / 4;   // 3136
    for (int t = c; t < n4; t += 256) o4[t] = s4[t];
}

// --------------------------------------------------------------------------
extern "C" void kernel_launch(void* const* d_in, const int* in_sizes, int n_in,
                              void* d_out, int out_size) {
    const float* fm   = (const float*)d_in[0];
    const int*   rois = (const int*)d_in[1];
    const int R = in_sizes[1] / 5;

    int img_off = out_size - R * C_ * O_ * O_;
    if (img_off < 0) img_off = 0;

    const int smem_bytes = C_ * O_ * O_ * (int)sizeof(float);   // 50176
    cudaFuncSetAttribute(roipool, cudaFuncAttributeMaxDynamicSharedMemorySize,
                         smem_bytes);

    dim3 gF(C_ / 8, K_CH, N_);
    fused_scan<<<gF, 160>>>(fm);

    const int tot = N_ * W_ * C_;
    chunk_carry<<<(tot + 255) / 256, 256>>>();

    roipool<<<R, 256, smem_bytes>>>(rois, (float*)d_out, img_off, R);
}

// round 4
// speedup vs baseline: 2.0938x; 1.7544x over previous
#include <cuda_runtime.h>

#define N_ 4
#define C_ 256
#define H_ 200
#define W_ 272
#define O_ 7
#define K_CH 8          // h-chunks
#define HCH 25          // H_ / K_CH

// Chunk-local 2D integral image, TRANSPOSED layout [n][h][w][c].
__device__ float g_integ[(size_t)N_ * H_ * W_ * C_];
// carry[n][k][w][c] = w-scanned column prefix of all chunks above k.
__device__ float g_carry[(size_t)N_ * K_CH * W_ * C_];

__device__ __forceinline__ float4 f4add(float4 a, float4 b) {
    return make_float4(a.x + b.x, a.y + b.y, a.z + b.z, a.w + b.w);
}
__device__ __forceinline__ float4 f4sub(float4 a, float4 b) {
    return make_float4(a.x - b.x, a.y - b.y, a.z - b.z, a.w - b.w);
}

// --------------------------------------------------------------------------
// Fused H-scan + W-scan + transpose, one pass.
// Block: 96 threads (3 warps), thread = 4 consecutive w (68 active).
// Block owns (n, h-chunk k, 8 channels). Per row: 8 float4 loads, H-scan in
// registers, in-thread 4-elem scan + warp shuffle scan of totals + smem
// block combine, 8x STG.128 c-major stores.
// --------------------------------------------------------------------------
__global__ __launch_bounds__(96) void fused_scan(const float* __restrict__ fm) {
    __shared__ float wsum[2][8][4];   // [buf][channel][warp], 3 warps used

    const int c0 = blockIdx.x * 8;
    const int k  = blockIdx.y;
    const int n  = blockIdx.z;
    const int slot = threadIdx.x;     // 0..95, active < 68
    const int lane = slot & 31;
    const int wid  = slot >> 5;       // 0..2
    const bool active = (slot < 68);
    const int w0 = slot * 4;

    float acc[8][4];
    #pragma unroll
    for (int j = 0; j < 8; ++j)
        #pragma unroll
        for (int e = 0; e < 4; ++e) acc[j][e] = 0.f;

    const float4* in0 = (const float4*)(fm + ((size_t)(n * C_ + c0) * H_
                          + (size_t)k * HCH) * W_) + (active ? slot : 0);
    const size_t out_base = (((size_t)n * H_ + (size_t)k * HCH) * W_) * C_ + c0;

    for (int lh = 0; lh < HCH; ++lh) {
        const int buf = lh & 1;
        float4 v[8];
        #pragma unroll
        for (int j = 0; j < 8; ++j)
            v[j] = in0[(size_t)j * (H_ * W_ / 4) + lh * (W_ / 4)];

        float sc[8][4];
        #pragma unroll
        for (int j = 0; j < 8; ++j) {
            if (!active) v[j] = make_float4(0.f, 0.f, 0.f, 0.f);
            acc[j][0] += v[j].x;
            acc[j][1] += v[j].y;
            acc[j][2] += v[j].z;
            acc[j][3] += v[j].w;
            // in-thread inclusive w-scan over 4 columns
            const float i0 = acc[j][0];
            const float i1 = i0 + acc[j][1];
            const float i2 = i1 + acc[j][2];
            const float i3 = i2 + acc[j][3];
            float x = i3;                         // warp inclusive scan on totals
            #pragma unroll
            for (int d = 1; d < 32; d <<= 1) {
                float y = __shfl_up_sync(0xffffffff, x, d);
                if (lane >= d) x += y;
            }
            const float excl = x - i3;
            sc[j][0] = i0 + excl;
            sc[j][1] = i1 + excl;
            sc[j][2] = i2 + excl;
            sc[j][3] = i3 + excl;
            if (lane == 31) wsum[buf][j][wid] = x;
        }
        __syncthreads();

        #pragma unroll
        for (int j = 0; j < 8; ++j) {
            float p = 0.f;
            #pragma unroll
            for (int t = 0; t < 2; ++t)
                if (t < wid) p += wsum[buf][j][t];
            #pragma unroll
            for (int e = 0; e < 4; ++e) sc[j][e] += p;
        }

        if (active) {
            float* dst = &g_integ[out_base + ((size_t)lh * W_ + w0) * C_];
            #pragma unroll
            for (int e = 0; e < 4; ++e) {
                float* d = dst + (size_t)e * C_;
                ((float4*)d)[0] = make_float4(sc[0][e], sc[1][e], sc[2][e], sc[3][e]);
                ((float4*)d)[1] = make_float4(sc[4][e], sc[5][e], sc[6][e], sc[7][e]);
            }
        }
    }
}

// --------------------------------------------------------------------------
// carry[n][k][w][c]: exclusive prefix over chunks of each chunk's last row.
// --------------------------------------------------------------------------
__global__ void chunk_carry() {
    const int total = N_ * W_ * C_;
    int idx = blockIdx.x * 256 + threadIdx.x;
    if (idx >= total) return;
    const int c = idx % C_;
    const int w = (idx / C_) % W_;
    const int n = idx / (C_ * W_);

    float p = 0.f;
    #pragma unroll
    for (int k = 0; k < K_CH; ++k) {
        g_carry[(((size_t)n * K_CH + k) * W_ + w) * C_ + c] = p;
        p += g_integ[(((size_t)n * H_ + (size_t)k * HCH + (HCH - 1)) * W_ + w) * C_ + c];
    }
}

// --------------------------------------------------------------------------
// Per-ROI gather. Block per ROI, 256 threads.
// Thread = (channel-quad cq = t&63, bin-group grp = t>>6). Each corner load
// is one float4 (4 channels) -> 4x fewer load instructions, same bytes.
// Results staged in smem, then written out coalesced (float4).
// --------------------------------------------------------------------------
__global__ void roipool(const int* __restrict__ rois, float* __restrict__ out,
                        int img_off, int R) {
    extern __shared__ float stage[];       // 256 * 49 floats
    __shared__ int sb[4 * O_];             // hs[7] he[7] ws[7] we[7]
    const int r = blockIdx.x;
    if (r >= R) return;
    const int t   = threadIdx.x;
    const int cq  = t & 63;
    const int grp = t >> 6;

    const int n  = rois[r * 5 + 0];
    const int x1 = rois[r * 5 + 1];
    const int y1 = rois[r * 5 + 2];
    const int x2 = rois[r * 5 + 3];
    const int y2 = rois[r * 5 + 4];

    if (t < O_) {
        const int hin = y2 - y1 + 1;
        const int win = x2 - x1 + 1;
        sb[t]          = y1 + (t * hin) / O_;                   // hs
        sb[O_ + t]     = y1 + ((t + 1) * hin + O_ - 1) / O_;    // he
        sb[2 * O_ + t] = x1 + (t * win) / O_;                   // ws
        sb[3 * O_ + t] = x1 + ((t + 1) * win + O_ - 1) / O_;    // we
    }
    __syncthreads();

    const float4* ib = (const float4*)g_integ + (size_t)n * (H_ * W_ * 64) + cq;
    const float4* cb = (const float4*)g_carry + (size_t)n * (K_CH * W_ * 64) + cq;
    const float4 z4 = make_float4(0.f, 0.f, 0.f, 0.f);

    if (img_off > 0 && t == 0) out[r] = (float)n;   // img_idx output

    #pragma unroll
    for (int m = 0; m < 13; ++m) {
        const int b = grp + 4 * m;
        if (b < O_ * O_) {
            const int i = b / O_;
            const int j = b - i * O_;
            const int hiT = sb[i];
            const int hiB = sb[O_ + i];
            const int wL  = sb[2 * O_ + j] - 1;   // may be -1 (pad)
            const int wR  = sb[3 * O_ + j] - 1;
            const int kB  = (hiB - 1) / HCH;
            const int kT  = (hiT > 0) ? (hiT - 1) / HCH : 0;

            float4 BR = f4add(ib[(size_t)((hiB - 1) * W_ + wR) * 64],
                              cb[(size_t)(kB * W_ + wR) * 64]);
            float4 TR = (hiT > 0)
                      ? f4add(ib[(size_t)((hiT - 1) * W_ + wR) * 64],
                              cb[(size_t)(kT * W_ + wR) * 64]) : z4;
            float4 BL = (wL >= 0)
                      ? f4add(ib[(size_t)((hiB - 1) * W_ + wL) * 64],
                              cb[(size_t)(kB * W_ + wL) * 64]) : z4;
            float4 TL = (hiT > 0 && wL >= 0)
                      ? f4add(ib[(size_t)((hiT - 1) * W_ + wL) * 64],
                              cb[(size_t)(kT * W_ + wL) * 64]) : z4;

            const float4 s = f4sub(f4sub(BR, TR), f4sub(BL, TL));
            const float inv = 1.f / ((float)(hiB - hiT) *
                                     (float)(sb[3 * O_ + j] - sb[2 * O_ + j]));
            const int base = (4 * cq) * (O_ * O_) + b;
            stage[base]                 = s.x * inv;
            stage[base + O_ * O_]       = s.y * inv;
            stage[base + 2 * (O_ * O_)] = s.z * inv;
            stage[base + 3 * (O_ * O_)] = s.w * inv;
        }
    }
    __syncthreads();

    // coalesced float4 writeout of the whole tile
    float4* o4 = (float4*)(out + img_off + (size_t)r * (C_ * O_ * O_));
    const float4* s4 = (const float4*)stage;
    const int n4 = C_ * O_ * O_ / 4;   // 3136
    for (int p = t; p < n4; p += 256) o4[p] = s4[p];
}

// --------------------------------------------------------------------------
extern "C" void kernel_launch(void* const* d_in, const int* in_sizes, int n_in,
                              void* d_out, int out_size) {
    const float* fm   = (const float*)d_in[0];
    const int*   rois = (const int*)d_in[1];
    const int R = in_sizes[1] / 5;

    int img_off = out_size - R * C_ * O_ * O_;
    if (img_off < 0) img_off = 0;

    const int smem_bytes = C_ * O_ * O_ * (int)sizeof(float);   // 50176
    cudaFuncSetAttribute(roipool, cudaFuncAttributeMaxDynamicSharedMemorySize,
                         smem_bytes);

    dim3 gF(C_ / 8, K_CH, N_);
    fused_scan<<<gF, 96>>>(fm);

    const int tot = N_ * W_ * C_;
    chunk_carry<<<(tot + 255) / 256, 256>>>();

    roipool<<<R, 256, smem_bytes>>>(rois, (float*)d_out, img_off, R);
}